// round 3
// baseline (speedup 1.0000x reference)
#include <cuda_runtime.h>

#define BB 16
#define CC 192
#define HH 64
#define WW 64
#define LL (HH*WW)      // 4096
#define RR 12           // dt_rank
#define NK 14           // dt_rank + 2*d_state

// Scratch (no cudaMalloc allowed)
__device__ float g_xs[(size_t)BB*CC*LL];      // 50.3 MB  conv+SiLU output
__device__ float g_delta[(size_t)BB*CC*LL];   // 50.3 MB  softplus(dt-proj)
__device__ float g_bc[(size_t)BB*2*LL];       // 0.5 MB   Bs, Cs rows

// ---------------------------------------------------------------------------
// K1: depthwise 5x5 conv (SAME) + bias + SiLU.
// One block per (b,c); 68x68 padded smem tile; circular 5x5 register window
// (constant indices after full unroll -> no register copies).
// ---------------------------------------------------------------------------
__global__ __launch_bounds__(256, 2) void conv_silu_kernel(
    const float* __restrict__ x,
    const float* __restrict__ cw,
    const float* __restrict__ cb)
{
    int bc = blockIdx.x;            // b*CC + c
    int c  = bc % CC;
    __shared__ float s[68 * 68];
    const float* img = x + (size_t)bc * LL;
    int tid = threadIdx.x;

    for (int idx = tid; idx < 68 * 68; idx += 256) {
        int yy = idx / 68, xx = idx % 68;
        int iy = yy - 2, ix = xx - 2;
        float v = 0.f;
        if (iy >= 0 && iy < HH && ix >= 0 && ix < WW) v = img[iy * WW + ix];
        s[idx] = v;
    }

    float w[25];
#pragma unroll
    for (int i = 0; i < 25; i++) w[i] = __ldg(&cw[c * 25 + i]);
    float bias = __ldg(&cb[c]);
    __syncthreads();

    int xcol = tid & 63;            // 0..63 (warp-contiguous)
    int y0   = (tid >> 6) * 16;     // 4 row-groups of 16
    float* dst = g_xs + (size_t)bc * LL;

    // circular window: at iter i, input row (y0+i+dy) lives in win[(i+dy)%5]
    float win[5][5];
#pragma unroll
    for (int j = 0; j < 4; j++)
#pragma unroll
        for (int dx = 0; dx < 5; dx++)
            win[j][dx] = s[(y0 + j) * 68 + xcol + dx];

#pragma unroll
    for (int i = 0; i < 16; i++) {
        int slot = (i + 4) % 5;
#pragma unroll
        for (int dx = 0; dx < 5; dx++)
            win[slot][dx] = s[(y0 + i + 4) * 68 + xcol + dx];

        float acc = bias;
#pragma unroll
        for (int dy = 0; dy < 5; dy++) {
            int r = (i + dy) % 5;   // constant after unroll
#pragma unroll
            for (int dx = 0; dx < 5; dx++)
                acc += win[r][dx] * w[dy * 5 + dx];
        }

        float e = exp2f(-acc * 1.44269504f);
        dst[(y0 + i) * WW + xcol] = __fdividef(acc, 1.f + e);
    }
}

// ---------------------------------------------------------------------------
// K2: fused x_proj + dt-projection + softplus.
// Even lanes reduce c in [0,96), odd lanes [96,192); partials combined via
// shfl_xor(1). Each thread owns 2 consecutive l's (float2).
// grid = (LL/256, BB), 256 threads.
// ---------------------------------------------------------------------------
__global__ __launch_bounds__(256) void xproj_delta_kernel(
    const float* __restrict__ xw,     // (14, C)
    const float* __restrict__ dtw,    // (C, 12)
    const float* __restrict__ dtb)    // (C,)
{
    __shared__ float sw[CC * 16];     // x_proj_w transposed (c,16) padded
    __shared__ float sdt[CC * RR];    // dt_w (c-major)
    __shared__ float sdb[CC];
    int t = threadIdx.x;
    for (int i = t; i < CC * 16; i += 256) sw[i] = 0.f;
    __syncthreads();
    for (int i = t; i < NK * CC; i += 256) {
        int k = i / CC, c = i % CC;
        sw[c * 16 + k] = xw[i];
    }
    for (int i = t; i < CC * RR; i += 256) sdt[i] = dtw[i];
    for (int i = t; i < CC; i += 256) sdb[i] = dtb[i];
    __syncthreads();

    int half = t & 1;                 // even: c<96, odd: c>=96
    int b = blockIdx.y;
    int l0 = blockIdx.x * 256 + (t >> 1) * 2;   // this thread's 2 l's
    const float* xs = g_xs + (size_t)b * CC * LL + l0;
    int c0 = half * 96;

    float accx[NK], accy[NK];
#pragma unroll
    for (int k = 0; k < NK; k++) { accx[k] = 0.f; accy[k] = 0.f; }

#pragma unroll 8
    for (int ci = 0; ci < 96; ci++) {
        int c = c0 + ci;
        float2 v = *(const float2*)(xs + (size_t)c * LL);
        const float* wp = &sw[c * 16];
#pragma unroll
        for (int k = 0; k < NK; k++) {
            float wk = wp[k];
            accx[k] = fmaf(wk, v.x, accx[k]);
            accy[k] = fmaf(wk, v.y, accy[k]);
        }
    }

    // combine halves (partner is lane^1)
#pragma unroll
    for (int k = 0; k < NK; k++) {
        accx[k] += __shfl_xor_sync(0xffffffffu, accx[k], 1);
        accy[k] += __shfl_xor_sync(0xffffffffu, accy[k], 1);
    }

    // Bs, Cs (once per l-pair)
    if (half == 0) {
        float* bcp = g_bc + (size_t)b * 2 * LL + l0;
        *(float2*)bcp        = make_float2(accx[12], accy[12]);
        *(float2*)(bcp + LL) = make_float2(accx[13], accy[13]);
    }

    // delta[c] for this lane's c-half, written coalesced per c
    float* dl = g_delta + (size_t)b * CC * LL + l0;
#pragma unroll 4
    for (int ci = 0; ci < 96; ci++) {
        int c = c0 + ci;
        const float* dwp = &sdt[c * RR];
        float dx = sdb[c], dy = sdb[c];
#pragma unroll
        for (int r = 0; r < RR; r++) {
            float wr = dwp[r];
            dx = fmaf(wr, accx[r], dx);
            dy = fmaf(wr, accy[r], dy);
        }
        float tx = __log2f(1.f + exp2f(dx * 1.44269504f)) * 0.69314718f;
        float ty = __log2f(1.f + exp2f(dy * 1.44269504f)) * 0.69314718f;
        float spx = (dx > 20.f) ? dx : tx;
        float spy = (dy > 20.f) ? dy : ty;
        *(float2*)(dl + (size_t)c * LL) = make_float2(spx, spy);
    }
}

// ---------------------------------------------------------------------------
// K3: selective scan (d_state=1) + output combine.
// One block of 256 threads per (b,c); thread owns 16 contiguous l's.
// Warp-shuffle scan of affine maps + 8-entry smem carry.
// ---------------------------------------------------------------------------
#define TPB3 256
#define SEG  16

__global__ __launch_bounds__(TPB3) void scan_kernel(
    const float* __restrict__ A_logs,
    const float* __restrict__ Ds,
    float* __restrict__ out)
{
    int bc = blockIdx.x;
    int b = bc / CC, c = bc % CC;
    int t = threadIdx.x;
    int lane = t & 31, wid = t >> 5;

    const float* xs_row = g_xs    + (size_t)bc * LL;
    const float* dl_row = g_delta + (size_t)bc * LL;
    const float* Bs_row = g_bc + (size_t)b * 2 * LL;
    const float* Cs_row = Bs_row + LL;

    float A  = -__expf(__ldg(&A_logs[c]));
    float Dv = __ldg(&Ds[c]);
    float Al2 = A * 1.44269504f;     // a = exp2(Al2 * delta)

    int l0 = t * SEG;

    float delta[SEG], xv[SEG];
    {
        const float4* pd = (const float4*)(dl_row + l0);
        const float4* px = (const float4*)(xs_row + l0);
#pragma unroll
        for (int j = 0; j < SEG / 4; j++) {
            float4 d = pd[j], v = px[j];
            delta[4*j+0]=d.x; delta[4*j+1]=d.y; delta[4*j+2]=d.z; delta[4*j+3]=d.w;
            xv[4*j+0]=v.x; xv[4*j+1]=v.y; xv[4*j+2]=v.z; xv[4*j+3]=v.w;
        }
    }

    // per-thread segment compose: h_out = Aseg*h_in + Bseg
    float Aseg = 1.f, Bseg = 0.f;
    const float4* pb = (const float4*)(Bs_row + l0);
#pragma unroll
    for (int j = 0; j < SEG / 4; j++) {
        float4 bv = pb[j];
        float bsv[4] = {bv.x, bv.y, bv.z, bv.w};
#pragma unroll
        for (int k = 0; k < 4; k++) {
            int i = 4 * j + k;
            float a  = exp2f(Al2 * delta[i]);
            float bt = delta[i] * bsv[k] * xv[i];
            Aseg = a * Aseg;
            Bseg = fmaf(a, Bseg, bt);
        }
    }

    // warp inclusive scan
#pragma unroll
    for (int off = 1; off < 32; off <<= 1) {
        float aU = __shfl_up_sync(0xffffffffu, Aseg, off);
        float bU = __shfl_up_sync(0xffffffffu, Bseg, off);
        if (lane >= off) { Bseg = fmaf(Aseg, bU, Bseg); Aseg *= aU; }
    }
    __shared__ float swA[TPB3/32], swB[TPB3/32];
    if (lane == 31) { swA[wid] = Aseg; swB[wid] = Bseg; }
    float aEx = __shfl_up_sync(0xffffffffu, Aseg, 1);
    float bEx = __shfl_up_sync(0xffffffffu, Bseg, 1);
    if (lane == 0) { aEx = 1.f; bEx = 0.f; }
    __syncthreads();
    float Bc = 0.f;
    for (int wp = 0; wp < wid; wp++) Bc = fmaf(swA[wp], Bc, swB[wp]);
    float h = fmaf(aEx, Bc, bEx);   // state entering this thread's segment

    float* out_row = out + (size_t)bc * LL + l0;
    const float4* pc = (const float4*)(Cs_row + l0);
#pragma unroll
    for (int j = 0; j < SEG / 4; j++) {
        float4 bv = pb[j];
        float4 cv = pc[j];
        float bsv[4] = {bv.x, bv.y, bv.z, bv.w};
        float csv[4] = {cv.x, cv.y, cv.z, cv.w};
        float yo[4];
#pragma unroll
        for (int k = 0; k < 4; k++) {
            int i = 4 * j + k;
            float a = exp2f(Al2 * delta[i]);
            h = fmaf(a, h, delta[i] * bsv[k] * xv[i]);
            yo[k] = fmaf(h, csv[k], xv[i] * Dv);
        }
        ((float4*)out_row)[j] = make_float4(yo[0], yo[1], yo[2], yo[3]);
    }
}

// ---------------------------------------------------------------------------
extern "C" void kernel_launch(void* const* d_in, const int* in_sizes, int n_in,
                              void* d_out, int out_size)
{
    const float* x        = (const float*)d_in[0];
    const float* conv_w   = (const float*)d_in[1];
    const float* conv_b   = (const float*)d_in[2];
    const float* x_proj_w = (const float*)d_in[3];
    const float* dt_w     = (const float*)d_in[4];
    const float* dt_b     = (const float*)d_in[5];
    const float* A_logs   = (const float*)d_in[6];
    const float* Ds       = (const float*)d_in[7];
    float* out = (float*)d_out;

    conv_silu_kernel<<<BB * CC, 256>>>(x, conv_w, conv_b);
    xproj_delta_kernel<<<dim3(LL / 256, BB), 256>>>(x_proj_w, dt_w, dt_b);
    scan_kernel<<<BB * CC, TPB3>>>(A_logs, Ds, out);
}

// round 4
// speedup vs baseline: 1.3371x; 1.3371x over previous
#include <cuda_runtime.h>

#define BB 16
#define CC 192
#define HH 64
#define WW 64
#define LL (HH*WW)      // 4096
#define RR 12           // dt_rank
#define NK 14           // dt_rank + 2*d_state

// Scratch (no cudaMalloc allowed)
__device__ float g_xs[(size_t)BB*CC*LL];      // 50.3 MB  conv+SiLU output
__device__ float g_delta[(size_t)BB*CC*LL];   // 50.3 MB  softplus(dt-proj)
__device__ float g_bc[(size_t)BB*2*LL];       // 0.5 MB   Bs, Cs rows

// ---------------------------------------------------------------------------
// K1: depthwise 5x5 conv (SAME) + bias + SiLU.  (R2 form: rolling window,
// regs<=40, high occupancy; dual accumulator chains for ILP.)
// ---------------------------------------------------------------------------
__global__ __launch_bounds__(256) void conv_silu_kernel(
    const float* __restrict__ x,
    const float* __restrict__ cw,
    const float* __restrict__ cb)
{
    int bc = blockIdx.x;            // b*CC + c
    int c  = bc % CC;
    __shared__ float s[68 * 68];
    const float* img = x + (size_t)bc * LL;
    int tid = threadIdx.x;

    for (int idx = tid; idx < 68 * 68; idx += 256) {
        int yy = idx / 68, xx = idx % 68;
        int iy = yy - 2, ix = xx - 2;
        float v = 0.f;
        if (iy >= 0 && iy < HH && ix >= 0 && ix < WW) v = img[iy * WW + ix];
        s[idx] = v;
    }

    float w[25];
#pragma unroll
    for (int i = 0; i < 25; i++) w[i] = __ldg(&cw[c * 25 + i]);
    float bias = __ldg(&cb[c]);
    __syncthreads();

    int xcol = tid & 63;            // 0..63 (warp-contiguous)
    int y0   = (tid >> 6) * 16;     // 4 row-groups of 16
    float* dst = g_xs + (size_t)bc * LL;

    float win[5][5];
#pragma unroll
    for (int dy = 0; dy < 4; dy++)
#pragma unroll
        for (int dx = 0; dx < 5; dx++)
            win[dy][dx] = s[(y0 + dy) * 68 + xcol + dx];

#pragma unroll
    for (int i = 0; i < 16; i++) {
        int y = y0 + i;
#pragma unroll
        for (int dx = 0; dx < 5; dx++)
            win[4][dx] = s[(y + 4) * 68 + xcol + dx];

        float acc0 = bias, acc1 = 0.f;
#pragma unroll
        for (int dy = 0; dy < 5; dy++) {
#pragma unroll
            for (int dx = 0; dx < 5; dx++) {
                float p = win[dy][dx] * 1.f;
                if (((dy * 5 + dx) & 1) == 0) acc0 = fmaf(win[dy][dx], w[dy*5+dx], acc0);
                else                          acc1 = fmaf(win[dy][dx], w[dy*5+dx], acc1);
                (void)p;
            }
        }
        float acc = acc0 + acc1;

        float e = exp2f(-acc * 1.44269504f);
        dst[y * WW + xcol] = __fdividef(acc, 1.f + e);

#pragma unroll
        for (int dy = 0; dy < 4; dy++)
#pragma unroll
            for (int dx = 0; dx < 5; dx++)
                win[dy][dx] = win[dy + 1][dx];
    }
}

// ---------------------------------------------------------------------------
// K2: fused x_proj + dt-projection + softplus (R3 lane-split form).
// ---------------------------------------------------------------------------
__global__ __launch_bounds__(256) void xproj_delta_kernel(
    const float* __restrict__ xw,     // (14, C)
    const float* __restrict__ dtw,    // (C, 12)
    const float* __restrict__ dtb)    // (C,)
{
    __shared__ float sw[CC * 16];
    __shared__ float sdt[CC * RR];
    __shared__ float sdb[CC];
    int t = threadIdx.x;
    for (int i = t; i < CC * 16; i += 256) sw[i] = 0.f;
    __syncthreads();
    for (int i = t; i < NK * CC; i += 256) {
        int k = i / CC, c = i % CC;
        sw[c * 16 + k] = xw[i];
    }
    for (int i = t; i < CC * RR; i += 256) sdt[i] = dtw[i];
    for (int i = t; i < CC; i += 256) sdb[i] = dtb[i];
    __syncthreads();

    int half = t & 1;                 // even: c<96, odd: c>=96
    int b = blockIdx.y;
    int l0 = blockIdx.x * 256 + (t >> 1) * 2;
    const float* xs = g_xs + (size_t)b * CC * LL + l0;
    int c0 = half * 96;

    float accx[NK], accy[NK];
#pragma unroll
    for (int k = 0; k < NK; k++) { accx[k] = 0.f; accy[k] = 0.f; }

#pragma unroll 8
    for (int ci = 0; ci < 96; ci++) {
        int c = c0 + ci;
        float2 v = *(const float2*)(xs + (size_t)c * LL);
        const float* wp = &sw[c * 16];
#pragma unroll
        for (int k = 0; k < NK; k++) {
            float wk = wp[k];
            accx[k] = fmaf(wk, v.x, accx[k]);
            accy[k] = fmaf(wk, v.y, accy[k]);
        }
    }

#pragma unroll
    for (int k = 0; k < NK; k++) {
        accx[k] += __shfl_xor_sync(0xffffffffu, accx[k], 1);
        accy[k] += __shfl_xor_sync(0xffffffffu, accy[k], 1);
    }

    if (half == 0) {
        float* bcp = g_bc + (size_t)b * 2 * LL + l0;
        *(float2*)bcp        = make_float2(accx[12], accy[12]);
        *(float2*)(bcp + LL) = make_float2(accx[13], accy[13]);
    }

    float* dl = g_delta + (size_t)b * CC * LL + l0;
#pragma unroll 4
    for (int ci = 0; ci < 96; ci++) {
        int c = c0 + ci;
        const float* dwp = &sdt[c * RR];
        float dx = sdb[c], dy = sdb[c];
#pragma unroll
        for (int r = 0; r < RR; r++) {
            float wr = dwp[r];
            dx = fmaf(wr, accx[r], dx);
            dy = fmaf(wr, accy[r], dy);
        }
        float tx = __log2f(1.f + exp2f(dx * 1.44269504f)) * 0.69314718f;
        float ty = __log2f(1.f + exp2f(dy * 1.44269504f)) * 0.69314718f;
        float spx = (dx > 20.f) ? dx : tx;
        float spy = (dy > 20.f) ? dy : ty;
        *(float2*)(dl + (size_t)c * LL) = make_float2(spx, spy);
    }
}

// ---------------------------------------------------------------------------
// K3: selective scan (d_state=1) + output, fully-coalesced warp-striped form.
// Block = one (b,c) row (L=4096), 256 threads = 8 warps, warp owns 512
// contiguous l's. Lane holds 4 chunks of 4 elems at l = wbase + j*128 + lane*4
// -> every LDG.128/STG.128 is 512B over 4 lines.
// Scan: per-chunk affine compose -> 4 chained warp scans -> 8-warp smem carry.
// ---------------------------------------------------------------------------
#define TPB3 256
#define NCH  4   // chunks per lane

__global__ __launch_bounds__(TPB3) void scan_kernel(
    const float* __restrict__ A_logs,
    const float* __restrict__ Ds,
    float* __restrict__ out)
{
    int bc = blockIdx.x;
    int b = bc / CC, c = bc % CC;
    int t = threadIdx.x;
    int lane = t & 31, wid = t >> 5;
    int wbase = wid * 512;

    const float* xs_row = g_xs    + (size_t)bc * LL;
    const float* dl_row = g_delta + (size_t)bc * LL;
    const float* Bs_row = g_bc + (size_t)b * 2 * LL;
    const float* Cs_row = Bs_row + LL;

    float A  = -__expf(__ldg(&A_logs[c]));
    float Dv = __ldg(&Ds[c]);
    float Al2 = A * 1.44269504f;

    // chunk j covers l = wbase + j*128 + lane*4 .. +3
    float dv[NCH][4], xv[NCH][4], bv[NCH][4];
    float Ain[NCH], Bin[NCH];       // affine state entering chunk (rel. warp start)

    float carryA = 1.f, carryB = 0.f;   // warp-local running compose

#pragma unroll
    for (int j = 0; j < NCH; j++) {
        int l = wbase + j * 128 + lane * 4;
        float4 d4 = *(const float4*)(dl_row + l);
        float4 x4 = *(const float4*)(xs_row + l);
        float4 b4 = *(const float4*)(Bs_row + l);
        dv[j][0]=d4.x; dv[j][1]=d4.y; dv[j][2]=d4.z; dv[j][3]=d4.w;
        xv[j][0]=x4.x; xv[j][1]=x4.y; xv[j][2]=x4.z; xv[j][3]=x4.w;
        bv[j][0]=b4.x; bv[j][1]=b4.y; bv[j][2]=b4.z; bv[j][3]=b4.w;

        // compose 4-elem chunk map
        float Ac = 1.f, Bc = 0.f;
#pragma unroll
        for (int k = 0; k < 4; k++) {
            float a  = exp2f(Al2 * dv[j][k]);
            float bt = dv[j][k] * bv[j][k] * xv[j][k];
            Ac = a * Ac;
            Bc = fmaf(a, Bc, bt);
        }

        // inclusive warp scan of chunk maps (earlier-lane-first compose)
        float Asc = Ac, Bsc = Bc;
#pragma unroll
        for (int off = 1; off < 32; off <<= 1) {
            float aU = __shfl_up_sync(0xffffffffu, Asc, off);
            float bU = __shfl_up_sync(0xffffffffu, Bsc, off);
            if (lane >= off) { Bsc = fmaf(Asc, bU, Bsc); Asc *= aU; }
        }
        // exclusive within this j
        float aEx = __shfl_up_sync(0xffffffffu, Asc, 1);
        float bEx = __shfl_up_sync(0xffffffffu, Bsc, 1);
        if (lane == 0) { aEx = 1.f; bEx = 0.f; }
        // entering state map = carry composed with exclusive
        Ain[j] = aEx * carryA;
        Bin[j] = fmaf(aEx, carryB, bEx);
        // update carry with j's total (lane 31 inclusive)
        float aT = __shfl_sync(0xffffffffu, Asc, 31);
        float bT = __shfl_sync(0xffffffffu, Bsc, 31);
        carryB = fmaf(aT, carryB, bT);
        carryA = aT * carryA;
    }

    // block-level carry across warps (h0 = 0 so only B matters)
    __shared__ float swA[TPB3/32], swB[TPB3/32];
    if (lane == 0) { swA[wid] = carryA; swB[wid] = carryB; }
    __syncthreads();
    float Hws = 0.f;
    for (int wp = 0; wp < wid; wp++) Hws = fmaf(swA[wp], Hws, swB[wp]);

    // replay + output
    float* out_row = out + (size_t)bc * LL;
#pragma unroll
    for (int j = 0; j < NCH; j++) {
        int l = wbase + j * 128 + lane * 4;
        float4 c4 = *(const float4*)(Cs_row + l);
        float csv[4] = {c4.x, c4.y, c4.z, c4.w};
        float h = fmaf(Ain[j], Hws, Bin[j]);
        float yo[4];
#pragma unroll
        for (int k = 0; k < 4; k++) {
            float a = exp2f(Al2 * dv[j][k]);
            h = fmaf(a, h, dv[j][k] * bv[j][k] * xv[j][k]);
            yo[k] = fmaf(h, csv[k], xv[j][k] * Dv);
        }
        *(float4*)(out_row + l) = make_float4(yo[0], yo[1], yo[2], yo[3]);
    }
}

// ---------------------------------------------------------------------------
extern "C" void kernel_launch(void* const* d_in, const int* in_sizes, int n_in,
                              void* d_out, int out_size)
{
    const float* x        = (const float*)d_in[0];
    const float* conv_w   = (const float*)d_in[1];
    const float* conv_b   = (const float*)d_in[2];
    const float* x_proj_w = (const float*)d_in[3];
    const float* dt_w     = (const float*)d_in[4];
    const float* dt_b     = (const float*)d_in[5];
    const float* A_logs   = (const float*)d_in[6];
    const float* Ds       = (const float*)d_in[7];
    float* out = (float*)d_out;

    conv_silu_kernel<<<BB * CC, 256>>>(x, conv_w, conv_b);
    xproj_delta_kernel<<<dim3(LL / 256, BB), 256>>>(x_proj_w, dt_w, dt_b);
    scan_kernel<<<BB * CC, TPB3>>>(A_logs, Ds, out);
}